// round 9
// baseline (speedup 1.0000x reference)
#include <cuda_runtime.h>
#include <cuda_fp16.h>
#include <cstdint>

// Propagate: 3-hop fixed-degree(16) CSR SpMM, N=100000, D=64 f32.
// out = A^3 x. indices/values arrive int32/f32 (JAX x64-disabled).
//
// R9: R5's fp16-gather / f32x2-accumulate body (best per-hop variant),
// with 4 sequential row-pairs per warp (contiguous). Fewer CTA waves
// (1563 blocks vs 6250) cuts the multi-CTA spread tail; sequential pairs
// let ptxas overlap pair k+1's edge loads/gathers with pair k's tail.
// Layout per pair: lanes 0..15 = row r0, lanes 16..31 = row r0+1; each
// lane owns 4 features (uint2 = 2x half2). Warp-wide LDG.64 gathers both
// rows' neighbor e (256B, 2 lines).

#define N_NODES 100000
#define DEG 16
#define D_FEAT 64
#define D_U2 (D_FEAT / 4)    // 16 uint2 (8B) per fp16 row
#define PAIRS 4
#define FULL 0xFFFFFFFFu

typedef unsigned long long ull;

__device__ __align__(256) __half g_hx[(size_t)N_NODES * D_FEAT];
__device__ __align__(256) __half g_h0[(size_t)N_NODES * D_FEAT];
__device__ __align__(256) __half g_h1[(size_t)N_NODES * D_FEAT];

__global__ void __launch_bounds__(256) to_half_kernel(
    const float2* __restrict__ in, __half2* __restrict__ out, int n2)
{
    int i = blockIdx.x * blockDim.x + threadIdx.x;
    if (i < n2) {
        float2 v = in[i];
        out[i] = __floats2half2_rn(v.x, v.y);
    }
}

template<bool OUT_F32>
__global__ void __launch_bounds__(256) hop_h_kernel(
    const uint2* __restrict__ xin,      // fp16 rows: 16 uint2 per row
    const float* __restrict__ values,
    const int*   __restrict__ indices,
    void* __restrict__ xout,
    int n_nodes)
{
    int gwarp = (blockIdx.x * blockDim.x + threadIdx.x) >> 5;
    int lane  = threadIdx.x & 31;

    int lane16 = lane & 15;
    int src_hi = lane & 16;             // 0 => even row of pair, 16 => odd
    int crow   = lane >> 4;

    int pair0 = gwarp * PAIRS;

#pragma unroll
    for (int p = 0; p < PAIRS; ++p) {
        int r0 = (pair0 + p) * 2;
        if (r0 >= n_nodes) break;

        // Lane l holds edge l of this row pair (coalesced).
        int eidx     = r0 * DEG + lane;
        int   nb_idx = indices[eidx];
        float ev     = values[eidx];

        ull a01 = 0ull, a23 = 0ull;

#pragma unroll
        for (int e = 0; e < DEG; ++e) {
            int   nb = __shfl_sync(FULL, nb_idx, src_hi | e);
            float w  = __shfl_sync(FULL, ev,     src_hi | e);

            uint2 hv = xin[(long long)nb * D_U2 + lane16];
            float2 f0 = __half22float2(*reinterpret_cast<__half2*>(&hv.x));
            float2 f1 = __half22float2(*reinterpret_cast<__half2*>(&hv.y));

            ull x01, x23, w2;
            asm("mov.b64 %0, {%1, %2};" : "=l"(x01) : "f"(f0.x), "f"(f0.y));
            asm("mov.b64 %0, {%1, %2};" : "=l"(x23) : "f"(f1.x), "f"(f1.y));
            asm("mov.b64 %0, {%1, %1};" : "=l"(w2)  : "f"(w));

            asm("fma.rn.f32x2 %0, %1, %2, %0;" : "+l"(a01) : "l"(x01), "l"(w2));
            asm("fma.rn.f32x2 %0, %1, %2, %0;" : "+l"(a23) : "l"(x23), "l"(w2));
        }

        float a0, a1, a2, a3;
        asm("mov.b64 {%0, %1}, %2;" : "=f"(a0), "=f"(a1) : "l"(a01));
        asm("mov.b64 {%0, %1}, %2;" : "=f"(a2), "=f"(a3) : "l"(a23));

        int r = r0 + crow;
        if (r < n_nodes) {
            if (OUT_F32) {
                ((float4*)xout)[(long long)r * 16 + lane16] =
                    make_float4(a0, a1, a2, a3);
            } else {
                __half2 o0 = __floats2half2_rn(a0, a1);
                __half2 o1 = __floats2half2_rn(a2, a3);
                uint2 o;
                o.x = *reinterpret_cast<uint32_t*>(&o0);
                o.y = *reinterpret_cast<uint32_t*>(&o1);
                ((uint2*)xout)[(long long)r * 16 + lane16] = o;
            }
        }
    }
}

extern "C" void kernel_launch(void* const* d_in, const int* in_sizes, int n_in,
                              void* d_out, int out_size)
{
    const float* x       = (const float*)d_in[0];   // [N, 64] f32
    const float* values  = (const float*)d_in[1];   // [E] f32
    // d_in[2] = indptr — fixed stride DEG, unused
    const int*   indices = (const int*)d_in[3];     // [E] int32
    float* out = (float*)d_out;

    int n_nodes = in_sizes[0] / D_FEAT;

    __half* hx; __half* h0; __half* h1;
    cudaGetSymbolAddress((void**)&hx, g_hx);
    cudaGetSymbolAddress((void**)&h0, g_h0);
    cudaGetSymbolAddress((void**)&h1, g_h1);

    int n2 = n_nodes * D_FEAT / 2;
    int cthreads = 256;
    int cblocks = (n2 + cthreads - 1) / cthreads;
    to_half_kernel<<<cblocks, cthreads>>>((const float2*)x, (__half2*)hx, n2);

    int threads = 256;
    int warps_per_block = threads / 32;
    int rows_per_block = warps_per_block * 2 * PAIRS;    // 64
    int blocks = (n_nodes + rows_per_block - 1) / rows_per_block;

    hop_h_kernel<false><<<blocks, threads>>>((const uint2*)hx, values, indices,
                                             (void*)h0, n_nodes);
    hop_h_kernel<false><<<blocks, threads>>>((const uint2*)h0, values, indices,
                                             (void*)h1, n_nodes);
    hop_h_kernel<true><<<blocks, threads>>>((const uint2*)h1, values, indices,
                                            (void*)out, n_nodes);
}

// round 10
// speedup vs baseline: 1.2744x; 1.2744x over previous
#include <cuda_runtime.h>
#include <cuda_fp16.h>
#include <cstdint>

// Propagate: 3-hop fixed-degree(16) CSR SpMM, N=100000, D=64 f32.
// out = A^3 x. indices/values arrive int32/f32 (JAX x64-disabled).
//
// Model (validated R5-R9): hop time == total L2 bytes / LTS cap (~11.3 TB/s).
// R10 removes bytes: edges packed once into uint32 = idx(17b) | val*2^15 (15b),
// cutting per-hop edge traffic 19.2MB -> 6.4MB. val in [0,1) so 15-bit
// fixed-point has abs err <= 3e-5 (negligible vs fp16's 3.6e-4).
// Gather body = R7's best: fp16 rows, LDG.128 fetching 2 edges x 2 rows
// (4 random 128B lines per instruction), f32x2 accumulation, 2 rows/warp
// (50k warps -- the TLP level that wins).

#define N_NODES 100000
#define DEG 16
#define D_FEAT 64
#define FULL 0xFFFFFFFFu

typedef unsigned long long ull;

__device__ __align__(256) __half g_hx[(size_t)N_NODES * D_FEAT];
__device__ __align__(256) __half g_h0[(size_t)N_NODES * D_FEAT];
__device__ __align__(256) __half g_h1[(size_t)N_NODES * D_FEAT];
__device__ unsigned g_edges[(size_t)N_NODES * DEG];   // idx<<15 | val15

// Prep: convert x -> fp16 (grid-stride over n2 half2) and pack edges.
__global__ void __launch_bounds__(256) prep_kernel(
    const float2* __restrict__ xin, __half2* __restrict__ hx, int n2,
    const int* __restrict__ indices, const float* __restrict__ values,
    unsigned* __restrict__ edges, int n_edges)
{
    int i = blockIdx.x * blockDim.x + threadIdx.x;
    if (i < n2) {
        float2 v = xin[i];
        hx[i] = __floats2half2_rn(v.x, v.y);
    }
    if (i < n_edges) {
        unsigned idx = (unsigned)indices[i];
        float    v   = values[i];                 // in [0,1)
        unsigned q   = (unsigned)(v * 32768.0f);  // 15-bit fixed point
        if (q > 32767u) q = 32767u;
        edges[i] = (idx << 15) | q;
    }
}

template<bool OUT_F32>
__global__ void __launch_bounds__(256) hop_h_kernel(
    const uint4* __restrict__ xin,      // fp16 rows: 8 uint4 (16B) per row
    const unsigned* __restrict__ edges,
    void* __restrict__ xout,
    int n_nodes)
{
    int gwarp = (blockIdx.x * blockDim.x + threadIdx.x) >> 5;
    int lane  = threadIdx.x & 31;

    int r0 = gwarp * 2;
    if (r0 >= n_nodes) return;

    int sub    = (lane >> 3) & 1;   // edge parity this lane gathers
    int feat8  = lane & 7;          // 16B feature slice
    int src_hi = lane & 16;         // 0 => row r0 edges, 16 => row r0+1

    // Lane l holds edge l of the row pair (coalesced 4B load, unpack once).
    unsigned p   = edges[r0 * DEG + lane];
    int   nb_idx = (int)(p >> 15);
    float ev     = (float)(p & 0x7FFFu) * (1.0f / 32768.0f);

    ull a01 = 0ull, a23 = 0ull, a45 = 0ull, a67 = 0ull;

#pragma unroll
    for (int i = 0; i < 8; ++i) {
        int   src = src_hi | (2 * i + sub);
        int   nb  = __shfl_sync(FULL, nb_idx, src);
        float w   = __shfl_sync(FULL, ev,     src);

        uint4 hv = xin[nb * 8 + feat8];        // 16B = 8 fp16 feats

        float2 f0 = __half22float2(*reinterpret_cast<__half2*>(&hv.x));
        float2 f1 = __half22float2(*reinterpret_cast<__half2*>(&hv.y));
        float2 f2 = __half22float2(*reinterpret_cast<__half2*>(&hv.z));
        float2 f3 = __half22float2(*reinterpret_cast<__half2*>(&hv.w));

        ull x01, x23, x45, x67, w2;
        asm("mov.b64 %0, {%1, %2};" : "=l"(x01) : "f"(f0.x), "f"(f0.y));
        asm("mov.b64 %0, {%1, %2};" : "=l"(x23) : "f"(f1.x), "f"(f1.y));
        asm("mov.b64 %0, {%1, %2};" : "=l"(x45) : "f"(f2.x), "f"(f2.y));
        asm("mov.b64 %0, {%1, %2};" : "=l"(x67) : "f"(f3.x), "f"(f3.y));
        asm("mov.b64 %0, {%1, %1};" : "=l"(w2)  : "f"(w));

        asm("fma.rn.f32x2 %0, %1, %2, %0;" : "+l"(a01) : "l"(x01), "l"(w2));
        asm("fma.rn.f32x2 %0, %1, %2, %0;" : "+l"(a23) : "l"(x23), "l"(w2));
        asm("fma.rn.f32x2 %0, %1, %2, %0;" : "+l"(a45) : "l"(x45), "l"(w2));
        asm("fma.rn.f32x2 %0, %1, %2, %0;" : "+l"(a67) : "l"(x67), "l"(w2));
    }

    float a[8];
    asm("mov.b64 {%0, %1}, %2;" : "=f"(a[0]), "=f"(a[1]) : "l"(a01));
    asm("mov.b64 {%0, %1}, %2;" : "=f"(a[2]), "=f"(a[3]) : "l"(a23));
    asm("mov.b64 {%0, %1}, %2;" : "=f"(a[4]), "=f"(a[5]) : "l"(a45));
    asm("mov.b64 {%0, %1}, %2;" : "=f"(a[6]), "=f"(a[7]) : "l"(a67));

    // Lanes l and l^8 hold the same feature slice over disjoint edge halves.
#pragma unroll
    for (int k = 0; k < 8; ++k)
        a[k] += __shfl_xor_sync(FULL, a[k], 8);

    if ((lane & 8) == 0) {
        int r = r0 + (lane >> 4);
        if (r < n_nodes) {
            if (OUT_F32) {
                float4* o = (float4*)xout;
                o[(long long)r * 16 + feat8 * 2 + 0] =
                    make_float4(a[0], a[1], a[2], a[3]);
                o[(long long)r * 16 + feat8 * 2 + 1] =
                    make_float4(a[4], a[5], a[6], a[7]);
            } else {
                __half2 h0 = __floats2half2_rn(a[0], a[1]);
                __half2 h1 = __floats2half2_rn(a[2], a[3]);
                __half2 h2 = __floats2half2_rn(a[4], a[5]);
                __half2 h3 = __floats2half2_rn(a[6], a[7]);
                uint4 o;
                o.x = *reinterpret_cast<uint32_t*>(&h0);
                o.y = *reinterpret_cast<uint32_t*>(&h1);
                o.z = *reinterpret_cast<uint32_t*>(&h2);
                o.w = *reinterpret_cast<uint32_t*>(&h3);
                ((uint4*)xout)[(long long)r * 8 + feat8] = o;
            }
        }
    }
}

extern "C" void kernel_launch(void* const* d_in, const int* in_sizes, int n_in,
                              void* d_out, int out_size)
{
    const float* x       = (const float*)d_in[0];   // [N, 64] f32
    const float* values  = (const float*)d_in[1];   // [E] f32
    // d_in[2] = indptr — fixed stride DEG, unused
    const int*   indices = (const int*)d_in[3];     // [E] int32
    float* out = (float*)d_out;

    int n_nodes = in_sizes[0] / D_FEAT;
    int n_edges = n_nodes * DEG;

    __half* hx; __half* h0; __half* h1; unsigned* edges;
    cudaGetSymbolAddress((void**)&hx, g_hx);
    cudaGetSymbolAddress((void**)&h0, g_h0);
    cudaGetSymbolAddress((void**)&h1, g_h1);
    cudaGetSymbolAddress((void**)&edges, g_edges);

    int n2 = n_nodes * D_FEAT / 2;
    int pthreads = 256;
    int pblocks = (n2 + pthreads - 1) / pthreads;   // n2 >= n_edges
    prep_kernel<<<pblocks, pthreads>>>((const float2*)x, (__half2*)hx, n2,
                                       indices, values, edges, n_edges);

    int threads = 256;
    int rows_per_block = (threads / 32) * 2;   // 2 rows per warp
    int blocks = (n_nodes + rows_per_block - 1) / rows_per_block;

    hop_h_kernel<false><<<blocks, threads>>>((const uint4*)hx, edges,
                                             (void*)h0, n_nodes);
    hop_h_kernel<false><<<blocks, threads>>>((const uint4*)h0, edges,
                                             (void*)h1, n_nodes);
    hop_h_kernel<true><<<blocks, threads>>>((const uint4*)h1, edges,
                                            (void*)out, n_nodes);
}